// round 13
// baseline (speedup 1.0000x reference)
#include <cuda_runtime.h>
#include <cstdint>

// Problem constants (fixed by the dataset)
#define NN 30000
#define EE 600000
#define HH 128
#define GG 64
#define LL 4

#define TILE 64        // rows per CTA (node / uv kernels)
#define ETILE 128      // edges per CTA (edge kernel, 512 threads)
#define AS 260         // node-kernel sA stride (words)
#define AS2 132        // split-plane stride for K=128 tiles
#define KSTAGE 32      // W stage depth (node / uv)
#define EKSTAGE 64     // W stage depth (edge kernel)

// Scratch (device globals: allocation-free rule)
__device__ __align__(16) float g_dist[EE];
__device__ __align__(16) float g_h[NN * HH];
__device__ __align__(16) float g_aggr[NN * HH];
__device__ __align__(16) float g_pool[GG * HH];
__device__ __align__(16) float g_U[NN * HH];   // h @ msgW1[0:128]   + b1
__device__ __align__(16) float g_V[NN * HH];   // h @ msgW1[128:256]

// Pre-split tf32 weights (hi/lo planes)
#define MSGW1_N (LL * 257 * HH)
#define MSGW2_N (LL * HH * HH)
#define NODW1_N (LL * 2 * HH * HH)
#define NODW2_N (LL * HH * HH)
__device__ __align__(16) uint32_t g_mw1h[MSGW1_N], g_mw1l[MSGW1_N];
__device__ __align__(16) uint32_t g_mw2h[MSGW2_N], g_mw2l[MSGW2_N];
__device__ __align__(16) uint32_t g_nw1h[NODW1_N], g_nw1l[NODW1_N];
__device__ __align__(16) uint32_t g_nw2h[NODW2_N], g_nw2l[NODW2_N];

__device__ __forceinline__ float silu_f(float x) {
    return __fdividef(x, 1.0f + __expf(-x));
}
__device__ __forceinline__ uint32_t f2tf32(float f) {
    uint32_t r; asm("cvt.rna.tf32.f32 %0, %1;" : "=r"(r) : "f"(f)); return r;
}
__device__ __forceinline__ void split_tf32(float v, uint32_t& hi, uint32_t& lo) {
    hi = f2tf32(v);
    lo = f2tf32(v - __uint_as_float(hi));
}
__device__ __forceinline__ void mma_tf32(float (&d)[4], const uint32_t (&a)[4],
                                         const uint32_t (&b)[2]) {
    asm volatile(
        "mma.sync.aligned.m16n8k8.row.col.f32.tf32.tf32.f32 "
        "{%0,%1,%2,%3}, {%4,%5,%6,%7}, {%8,%9}, {%0,%1,%2,%3};"
        : "+f"(d[0]), "+f"(d[1]), "+f"(d[2]), "+f"(d[3])
        : "r"(a[0]), "r"(a[1]), "r"(a[2]), "r"(a[3]), "r"(b[0]), "r"(b[1]));
}
__device__ __forceinline__ void red2(float* p, float a, float b) {
    asm volatile("red.global.add.v2.f32 [%0], {%1,%2};" :: "l"(p), "f"(a), "f"(b) : "memory");
}
__device__ __forceinline__ void red4(float* p, float a, float b, float c, float d) {
    asm volatile("red.global.add.v4.f32 [%0], {%1,%2,%3,%4};"
                 :: "l"(p), "f"(a), "f"(b), "f"(c), "f"(d) : "memory");
}

__global__ void k_split(const float* __restrict__ src, uint32_t* __restrict__ hi,
                        uint32_t* __restrict__ lo, int n) {
    int i = blockIdx.x * blockDim.x + threadIdx.x;
    if (i >= n) return;
    uint32_t h, l;
    split_tf32(src[i], h, l);
    hi[i] = h; lo[i] = l;
}

// Stage 32 k-rows of pre-split W into sW planes with XOR swizzle (256 threads).
__device__ __forceinline__ void stage_W(float* sWh, float* sWl,
                                        const uint32_t* __restrict__ wh,
                                        const uint32_t* __restrict__ wl,
                                        int k0, int tid) {
    #pragma unroll
    for (int i = 0; i < 4; i++) {
        int k = (tid >> 5) + 8 * i;          // 0..31
        int n0 = (tid & 31) * 4;
        uint4 vh = *(const uint4*)(wh + (size_t)(k0 + k) * HH + n0);
        uint4 vl = *(const uint4*)(wl + (size_t)(k0 + k) * HH + n0);
        int d = k * HH + (n0 ^ ((k & 3) << 3));
        *(uint4*)(sWh + d) = vh;
        *(uint4*)(sWl + d) = vl;
    }
}

// 512-thread variant: stages EKSTAGE=64 rows.
__device__ __forceinline__ void stage_W512(float* sWh, float* sWl,
                                           const uint32_t* __restrict__ wh,
                                           const uint32_t* __restrict__ wl,
                                           int k0, int tid) {
    #pragma unroll
    for (int i = 0; i < 4; i++) {
        int k = (tid >> 5) + 16 * i;         // 0..63
        int n0 = (tid & 31) * 4;
        uint4 vh = *(const uint4*)(wh + (size_t)(k0 + k) * HH + n0);
        uint4 vl = *(const uint4*)(wl + (size_t)(k0 + k) * HH + n0);
        int d = k * HH + (n0 ^ ((k & 3) << 3));
        *(uint4*)(sWh + d) = vh;
        *(uint4*)(sWl + d) = vl;
    }
}

// One k8 step with PRE-SPLIT A planes (stride AS2): pure LDS+HMMA.
__device__ __forceinline__ void mma_k8ps(const float* sAh, const float* sAl,
                                         const float* sWh, const float* sWl,
                                         int mbase, int nbase, int kg, int kw,
                                         int gid, int kk, float (&acc)[2][4][4]) {
    uint32_t ah[2][4], al[2][4];
    #pragma unroll
    for (int i = 0; i < 2; i++) {
        int base = (mbase + i * 16 + gid) * AS2 + kg + kk;
        ah[i][0] = __float_as_uint(sAh[base]);
        ah[i][1] = __float_as_uint(sAh[base + 8 * AS2]);
        ah[i][2] = __float_as_uint(sAh[base + 4]);
        ah[i][3] = __float_as_uint(sAh[base + 8 * AS2 + 4]);
        al[i][0] = __float_as_uint(sAl[base]);
        al[i][1] = __float_as_uint(sAl[base + 8 * AS2]);
        al[i][2] = __float_as_uint(sAl[base + 4]);
        al[i][3] = __float_as_uint(sAl[base + 8 * AS2 + 4]);
    }
    const int rb = (kw + kk) * HH;
    #pragma unroll
    for (int j = 0; j < 4; j++) {
        int nsw = rb + ((nbase + j * 8 + gid) ^ (kk << 3));
        uint32_t bh[2], bl[2];
        bh[0] = __float_as_uint(sWh[nsw]);
        bh[1] = __float_as_uint(sWh[4 * HH + nsw]);
        bl[0] = __float_as_uint(sWl[nsw]);
        bl[1] = __float_as_uint(sWl[4 * HH + nsw]);
        mma_tf32(acc[0][j], ah[0], bh);
        mma_tf32(acc[0][j], ah[0], bl);
        mma_tf32(acc[0][j], al[0], bh);
        mma_tf32(acc[1][j], ah[1], bh);
        mma_tf32(acc[1][j], ah[1], bl);
        mma_tf32(acc[1][j], al[1], bh);
    }
}

// In-loop-split variant (node kernel; A fp32, stride AS).
__device__ __forceinline__ void mma_k8(const float* sA, const float* sWh, const float* sWl,
                                       int mbase, int nbase, int kg, int kw,
                                       int gid, int kk, float (&acc)[2][4][4]) {
    uint32_t ah[2][4], al[2][4];
    #pragma unroll
    for (int i = 0; i < 2; i++) {
        const float* ra = sA + (mbase + i * 16 + gid) * AS + kg + kk;
        split_tf32(ra[0],          ah[i][0], al[i][0]);
        split_tf32(ra[8 * AS],     ah[i][1], al[i][1]);
        split_tf32(ra[4],          ah[i][2], al[i][2]);
        split_tf32(ra[8 * AS + 4], ah[i][3], al[i][3]);
    }
    const int rb = (kw + kk) * HH;
    #pragma unroll
    for (int j = 0; j < 4; j++) {
        int nsw = rb + ((nbase + j * 8 + gid) ^ (kk << 3));
        uint32_t bh[2], bl[2];
        bh[0] = __float_as_uint(sWh[nsw]);
        bh[1] = __float_as_uint(sWh[4 * HH + nsw]);
        bl[0] = __float_as_uint(sWl[nsw]);
        bl[1] = __float_as_uint(sWl[4 * HH + nsw]);
        mma_tf32(acc[0][j], ah[0], bh);
        mma_tf32(acc[0][j], ah[0], bl);
        mma_tf32(acc[0][j], al[0], bh);
        mma_tf32(acc[1][j], ah[1], bh);
        mma_tf32(acc[1][j], ah[1], bl);
        mma_tf32(acc[1][j], al[1], bh);
    }
}

// ---------------------------------------------------------------------------
__global__ void k_dist(const float* __restrict__ pos, const int* __restrict__ ei) {
    int e = blockIdx.x * blockDim.x + threadIdx.x;
    if (e >= EE) return;
    int r = ei[e], c = ei[EE + e];
    float dx = pos[r * 3 + 0] - pos[c * 3 + 0];
    float dy = pos[r * 3 + 1] - pos[c * 3 + 1];
    float dz = pos[r * 3 + 2] - pos[c * 3 + 2];
    g_dist[e] = dx * dx + dy * dy + dz * dz;
}
__global__ void k_embed(const float* __restrict__ x, const float* __restrict__ w,
                        const float* __restrict__ b) {
    int i = blockIdx.x * blockDim.x + threadIdx.x;
    if (i >= NN * HH) return;
    int n = i >> 7, c = i & 127;
    g_h[i] = x[n] * w[c] + b[c];
}
__global__ void k_zero_pool() {
    int i = blockIdx.x * blockDim.x + threadIdx.x;
    if (i < GG * HH) g_pool[i] = 0.0f;
}

// ---------------------------------------------------------------------------
// Per-node precompute: U = h @ W1[0:128] + b1, V = h @ W1[128:256].
// Also zeroes g_aggr for this node tile (replaces k_zero_aggr).
__global__ __launch_bounds__(256) void k_uv(
    const uint32_t* __restrict__ w1h, const uint32_t* __restrict__ w1l,
    const float* __restrict__ b1)
{
    extern __shared__ float sm[];
    float* sAh = sm;                         // TILE*AS2
    float* sAl = sAh + TILE * AS2;
    float* sWh = sAl + TILE * AS2;           // KSTAGE*HH
    float* sWl = sWh + KSTAGE * HH;
    float* sB1 = sWl + KSTAGE * HH;          // 128

    const int tid = threadIdx.x, wid = tid >> 5, lane = tid & 31;
    const int kk = lane & 3, gid = lane >> 2;
    const int mbase = (wid & 1) * 32;
    const int nbase = (wid >> 1) * 32;
    const int rbase = blockIdx.x * TILE;

    #pragma unroll
    for (int i = 0; i < 8; i++) {
        int m = wid * 8 + i;
        int n = rbase + m;
        float4 v = make_float4(0.f, 0.f, 0.f, 0.f);
        if (n < NN) v = *(const float4*)(g_h + (size_t)n * HH + lane * 4);
        uint4 qh, ql;
        split_tf32(v.x, qh.x, ql.x); split_tf32(v.y, qh.y, ql.y);
        split_tf32(v.z, qh.z, ql.z); split_tf32(v.w, qh.w, ql.w);
        *(uint4*)(sAh + m * AS2 + lane * 4) = qh;
        *(uint4*)(sAl + m * AS2 + lane * 4) = ql;
        if (n < NN)
            *(float4*)(g_aggr + (size_t)n * HH + lane * 4) = make_float4(0.f, 0.f, 0.f, 0.f);
    }
    if (tid < HH) sB1[tid] = b1[tid];
    __syncthreads();

    #pragma unroll
    for (int pass = 0; pass < 2; pass++) {
        const uint32_t* wh = w1h + (size_t)pass * 128 * HH;
        const uint32_t* wl = w1l + (size_t)pass * 128 * HH;
        float acc[2][4][4];
        #pragma unroll
        for (int j = 0; j < 4; j++) {
            int col = nbase + j * 8 + kk * 2;
            float v0 = pass ? 0.f : sB1[col];
            float v1 = pass ? 0.f : sB1[col + 1];
            acc[0][j][0] = v0; acc[0][j][1] = v1; acc[0][j][2] = v0; acc[0][j][3] = v1;
            acc[1][j][0] = v0; acc[1][j][1] = v1; acc[1][j][2] = v0; acc[1][j][3] = v1;
        }
        for (int st = 0; st < 4; st++) {
            int k0 = st * KSTAGE;
            __syncthreads();
            stage_W(sWh, sWl, wh, wl, k0, tid);
            __syncthreads();
            #pragma unroll
            for (int c = 0; c < 4; c++)
                mma_k8ps(sAh, sAl, sWh, sWl, mbase, nbase, k0 + c * 8, c * 8, gid, kk, acc);
        }
        float* dst = pass ? g_V : g_U;
        #pragma unroll
        for (int i = 0; i < 2; i++) {
            int r0 = mbase + i * 16 + gid, r1 = r0 + 8;
            int n0 = rbase + r0, n1 = rbase + r1;
            #pragma unroll
            for (int j = 0; j < 4; j++) {
                int col = nbase + j * 8 + kk * 2;
                if (n0 < NN)
                    *(float2*)(dst + (size_t)n0 * HH + col) = make_float2(acc[i][j][0], acc[i][j][1]);
                if (n1 < NN)
                    *(float2*)(dst + (size_t)n1 * HH + col) = make_float2(acc[i][j][2], acc[i][j][3]);
            }
        }
    }
}

// ---------------------------------------------------------------------------
// Edge kernel: 128 edges/CTA, 512 threads (16 warps, 4M x 4N).
// pre = U[dst]+V[src]+d2*w1r -> silu -> split -> GEMM2 (K=128) -> scatter.
__global__ __launch_bounds__(512) void k_edge(
    const int* __restrict__ ei,
    const uint32_t* __restrict__ w2h, const uint32_t* __restrict__ w2l,
    const float* __restrict__ w1, const float* __restrict__ b2)
{
    extern __shared__ float sm[];
    float* sAh = sm;                          // ETILE*AS2
    float* sAl = sAh + ETILE * AS2;
    float* sWh = sAl + ETILE * AS2;           // EKSTAGE*HH
    float* sWl = sWh + EKSTAGE * HH;
    int* sCol = (int*)(sWl + EKSTAGE * HH);   // 128
    float* sW1r = (float*)(sCol + ETILE);     // 128
    float* sB2 = sW1r + HH;                   // 128

    const int tid = threadIdx.x, wid = tid >> 5, lane = tid & 31;
    const int kk = lane & 3, gid = lane >> 2;
    const int mbase = (wid & 3) * 32;
    const int nbase = (wid >> 2) * 32;
    const int e0 = blockIdx.x * ETILE;

    if (tid < HH) {
        sW1r[tid] = w1[(size_t)256 * HH + tid];
        sB2[tid] = b2[tid];
    }
    __syncthreads();

    // gather + message pre-activation + silu + split (16 warps x 8 rows)
    #pragma unroll
    for (int i = 0; i < 8; i++) {
        int m = wid * 8 + i;
        int e = e0 + m;
        uint4 qh = make_uint4(0, 0, 0, 0), ql = qh;
        if (e < EE) {
            int src = ei[e], dst = ei[EE + e];
            if (lane == 0) sCol[m] = dst;
            float d = g_dist[e];
            float4 u = *(const float4*)(g_U + (size_t)dst * HH + lane * 4);
            float4 v = *(const float4*)(g_V + (size_t)src * HH + lane * 4);
            float4 wr = *(const float4*)(sW1r + lane * 4);
            float4 t;
            t.x = silu_f(u.x + v.x + d * wr.x);
            t.y = silu_f(u.y + v.y + d * wr.y);
            t.z = silu_f(u.z + v.z + d * wr.z);
            t.w = silu_f(u.w + v.w + d * wr.w);
            split_tf32(t.x, qh.x, ql.x); split_tf32(t.y, qh.y, ql.y);
            split_tf32(t.z, qh.z, ql.z); split_tf32(t.w, qh.w, ql.w);
        } else if (lane == 0) {
            sCol[m] = -1;
        }
        *(uint4*)(sAh + m * AS2 + lane * 4) = qh;
        *(uint4*)(sAl + m * AS2 + lane * 4) = ql;
    }
    __syncthreads();

    float acc[2][4][4];
    #pragma unroll
    for (int j = 0; j < 4; j++) {
        int col = nbase + j * 8 + kk * 2;
        float v0 = sB2[col], v1 = sB2[col + 1];
        acc[0][j][0] = v0; acc[0][j][1] = v1; acc[0][j][2] = v0; acc[0][j][3] = v1;
        acc[1][j][0] = v0; acc[1][j][1] = v1; acc[1][j][2] = v0; acc[1][j][3] = v1;
    }

    // GEMM2: K = 128 in 2 stages of EKSTAGE=64
    #pragma unroll
    for (int st = 0; st < 2; st++) {
        int k0 = st * EKSTAGE;
        __syncthreads();
        stage_W512(sWh, sWl, w2h, w2l, k0, tid);
        __syncthreads();
        #pragma unroll
        for (int c = 0; c < 8; c++)
            mma_k8ps(sAh, sAl, sWh, sWl, mbase, nbase, k0 + c * 8, c * 8, gid, kk, acc);
    }

    // scatter-add into g_aggr[dst]
    #pragma unroll
    for (int i = 0; i < 2; i++) {
        int r0 = mbase + i * 16 + gid, r1 = r0 + 8;
        int c0 = sCol[r0], c1 = sCol[r1];
        float* p0 = g_aggr + (size_t)(c0 < 0 ? 0 : c0) * HH;
        float* p1 = g_aggr + (size_t)(c1 < 0 ? 0 : c1) * HH;
        #pragma unroll
        for (int j = 0; j < 4; j++) {
            int col = nbase + j * 8 + kk * 2;
            if (c0 >= 0) red2(p0 + col, acc[i][j][0], acc[i][j][1]);
            if (c1 >= 0) red2(p1 + col, acc[i][j][2], acc[i][j][3]);
        }
    }
}

// ---------------------------------------------------------------------------
// Fused node MLP (3xTF32 mma.sync, pre-split W). A = [h | aggr], 64 nodes/CTA.
__global__ __launch_bounds__(256) void k_node(
    const uint32_t* __restrict__ w1h, const uint32_t* __restrict__ w1l,
    const uint32_t* __restrict__ w2h, const uint32_t* __restrict__ w2l,
    const float* __restrict__ b1, const float* __restrict__ b2)
{
    extern __shared__ float sm[];
    float* sA = sm;
    float* sWh = sm + TILE * AS;
    float* sWl = sWh + KSTAGE * HH;
    float* sB1 = sWl + KSTAGE * HH;
    float* sB2 = sB1 + HH;

    const int tid = threadIdx.x, wid = tid >> 5, lane = tid & 31;
    const int kk = lane & 3, gid = lane >> 2;
    const int mbase = (wid & 1) * 32;
    const int nbase = (wid >> 1) * 32;
    const int rbase = blockIdx.x * TILE;

    #pragma unroll
    for (int i = 0; i < 8; i++) {
        int m = wid * 8 + i;
        int n = rbase + m;
        float4 vh = make_float4(0.f, 0.f, 0.f, 0.f), va = vh;
        if (n < NN) {
            vh = *(const float4*)(g_h + (size_t)n * HH + lane * 4);
            va = *(const float4*)(g_aggr + (size_t)n * HH + lane * 4);
        }
        *(float4*)(sA + m * AS + lane * 4) = vh;
        *(float4*)(sA + m * AS + 128 + lane * 4) = va;
    }
    if (tid < HH) { sB1[tid] = b1[tid]; sB2[tid] = b2[tid]; }
    __syncthreads();

    float acc[2][4][4];
    #pragma unroll
    for (int j = 0; j < 4; j++) {
        int col = nbase + j * 8 + kk * 2;
        float v0 = sB1[col], v1 = sB1[col + 1];
        acc[0][j][0] = v0; acc[0][j][1] = v1; acc[0][j][2] = v0; acc[0][j][3] = v1;
        acc[1][j][0] = v0; acc[1][j][1] = v1; acc[1][j][2] = v0; acc[1][j][3] = v1;
    }

    for (int st = 0; st < 8; st++) {
        int k0 = st * KSTAGE;
        __syncthreads();
        stage_W(sWh, sWl, w1h, w1l, k0, tid);
        __syncthreads();
        #pragma unroll
        for (int c = 0; c < 4; c++)
            mma_k8(sA, sWh, sWl, mbase, nbase, k0 + c * 8, c * 8, gid, kk, acc);
    }
    __syncthreads();

    #pragma unroll
    for (int i = 0; i < 2; i++) {
        int r0 = mbase + i * 16 + gid, r1 = r0 + 8;
        #pragma unroll
        for (int j = 0; j < 4; j++) {
            int col = nbase + j * 8 + kk * 2;
            float t0 = silu_f(acc[i][j][0]);
            float t1 = silu_f(acc[i][j][1]);
            float t2 = silu_f(acc[i][j][2]);
            float t3 = silu_f(acc[i][j][3]);
            *(float2*)(sA + r0 * AS + col) = make_float2(t0, t1);
            *(float2*)(sA + r1 * AS + col) = make_float2(t2, t3);
            float b0 = sB2[col], b1v = sB2[col + 1];
            acc[i][j][0] = b0; acc[i][j][1] = b1v; acc[i][j][2] = b0; acc[i][j][3] = b1v;
        }
    }

    for (int st = 0; st < 4; st++) {
        int k0 = st * KSTAGE;
        __syncthreads();
        stage_W(sWh, sWl, w2h, w2l, k0, tid);
        __syncthreads();
        #pragma unroll
        for (int c = 0; c < 4; c++)
            mma_k8(sA, sWh, sWl, mbase, nbase, k0 + c * 8, c * 8, gid, kk, acc);
    }

    #pragma unroll
    for (int i = 0; i < 2; i++) {
        int r0 = mbase + i * 16 + gid, r1 = r0 + 8;
        int n0 = rbase + r0, n1 = rbase + r1;
        #pragma unroll
        for (int j = 0; j < 4; j++) {
            int col = nbase + j * 8 + kk * 2;
            if (n0 < NN)
                *(float2*)(g_h + (size_t)n0 * HH + col) = make_float2(acc[i][j][0], acc[i][j][1]);
            if (n1 < NN)
                *(float2*)(g_h + (size_t)n1 * HH + col) = make_float2(acc[i][j][2], acc[i][j][3]);
        }
    }
}

// ---------------------------------------------------------------------------
__global__ void k_pool(const int* __restrict__ batch) {
    int i = blockIdx.x * blockDim.x + threadIdx.x;
    if (i >= NN * 32) return;
    int n = i >> 5, c4 = (i & 31) * 4;
    int b = batch[n];
    const float* hr = g_h + (size_t)n * HH + c4;
    red4(g_pool + (size_t)b * HH + c4, hr[0], hr[1], hr[2], hr[3]);
}

__global__ void k_out(const float* __restrict__ w1, const float* __restrict__ b1,
                      const float* __restrict__ w2, const float* __restrict__ b2,
                      float* __restrict__ out) {
    __shared__ float sg[GG * HH];
    __shared__ float sh[GG * 32];
    int tid = threadIdx.x;
    for (int i = tid; i < GG * HH; i += 256) sg[i] = g_pool[i];
    __syncthreads();
    for (int p = tid; p < GG * 32; p += 256) {
        int g = p >> 5, j = p & 31;
        float s = b1[j];
        #pragma unroll 4
        for (int k = 0; k < HH; k++) s += sg[g * HH + k] * w1[k * 32 + j];
        sh[p] = silu_f(s);
    }
    __syncthreads();
    if (tid < GG) {
        float s = b2[0];
        #pragma unroll
        for (int j = 0; j < 32; j++) s += sh[tid * 32 + j] * w2[j];
        out[tid] = s;
    }
}

// ---------------------------------------------------------------------------
extern "C" void kernel_launch(void* const* d_in, const int* in_sizes, int n_in,
                              void* d_out, int out_size) {
    const float* x       = (const float*)d_in[0];
    const float* pos     = (const float*)d_in[1];
    const int*   ei      = (const int*)d_in[2];
    const int*   batch   = (const int*)d_in[3];
    const float* emb_w   = (const float*)d_in[4];
    const float* emb_b   = (const float*)d_in[5];
    const float* msg_w1  = (const float*)d_in[6];
    const float* msg_b1  = (const float*)d_in[7];
    const float* msg_w2  = (const float*)d_in[8];
    const float* msg_b2  = (const float*)d_in[9];
    const float* node_w1 = (const float*)d_in[10];
    const float* node_b1 = (const float*)d_in[11];
    const float* node_w2 = (const float*)d_in[12];
    const float* node_b2 = (const float*)d_in[13];
    const float* out_w1  = (const float*)d_in[14];
    const float* out_b1  = (const float*)d_in[15];
    const float* out_w2  = (const float*)d_in[16];
    const float* out_b2  = (const float*)d_in[17];
    float* out = (float*)d_out;

    const int SMEM_UV   = (2 * TILE * AS2 + 2 * KSTAGE * HH + HH) * 4;
    const int SMEM_EDGE = (2 * ETILE * AS2 + 2 * EKSTAGE * HH) * 4 + ETILE * 4 + 2 * HH * 4;
    const int SMEM_NODE = (TILE * AS + 2 * KSTAGE * HH) * 4 + 2 * HH * 4;
    cudaFuncSetAttribute(k_uv, cudaFuncAttributeMaxDynamicSharedMemorySize, SMEM_UV);
    cudaFuncSetAttribute(k_edge, cudaFuncAttributeMaxDynamicSharedMemorySize, SMEM_EDGE);
    cudaFuncSetAttribute(k_node, cudaFuncAttributeMaxDynamicSharedMemorySize, SMEM_NODE);

    void *mw1h, *mw1l, *mw2h, *mw2l, *nw1h, *nw1l, *nw2h, *nw2l;
    cudaGetSymbolAddress(&mw1h, g_mw1h); cudaGetSymbolAddress(&mw1l, g_mw1l);
    cudaGetSymbolAddress(&mw2h, g_mw2h); cudaGetSymbolAddress(&mw2l, g_mw2l);
    cudaGetSymbolAddress(&nw1h, g_nw1h); cudaGetSymbolAddress(&nw1l, g_nw1l);
    cudaGetSymbolAddress(&nw2h, g_nw2h); cudaGetSymbolAddress(&nw2l, g_nw2l);

    k_split<<<(MSGW1_N + 255) / 256, 256>>>(msg_w1, (uint32_t*)mw1h, (uint32_t*)mw1l, MSGW1_N);
    k_split<<<(MSGW2_N + 255) / 256, 256>>>(msg_w2, (uint32_t*)mw2h, (uint32_t*)mw2l, MSGW2_N);
    k_split<<<(NODW1_N + 255) / 256, 256>>>(node_w1, (uint32_t*)nw1h, (uint32_t*)nw1l, NODW1_N);
    k_split<<<(NODW2_N + 255) / 256, 256>>>(node_w2, (uint32_t*)nw2h, (uint32_t*)nw2l, NODW2_N);

    k_dist<<<(EE + 255) / 256, 256>>>(pos, ei);
    k_embed<<<(NN * HH + 255) / 256, 256>>>(x, emb_w, emb_b);

    const int EGRID = (EE + ETILE - 1) / ETILE;  // 4688
    const int NGRID = (NN + TILE - 1) / TILE;    // 469

    for (int l = 0; l < LL; l++) {
        k_uv<<<NGRID, 256, SMEM_UV>>>(
            (const uint32_t*)mw1h + (size_t)l * 257 * HH,
            (const uint32_t*)mw1l + (size_t)l * 257 * HH,
            msg_b1 + (size_t)l * HH);
        k_edge<<<EGRID, 512, SMEM_EDGE>>>(
            ei,
            (const uint32_t*)mw2h + (size_t)l * HH * HH,
            (const uint32_t*)mw2l + (size_t)l * HH * HH,
            msg_w1 + (size_t)l * 257 * HH,
            msg_b2 + (size_t)l * HH);
        k_node<<<NGRID, 256, SMEM_NODE>>>(
            (const uint32_t*)nw1h + (size_t)l * 2 * HH * HH,
            (const uint32_t*)nw1l + (size_t)l * 2 * HH * HH,
            (const uint32_t*)nw2h + (size_t)l * HH * HH,
            (const uint32_t*)nw2l + (size_t)l * HH * HH,
            node_b1 + (size_t)l * HH, node_b2 + (size_t)l * HH);
    }

    k_zero_pool<<<(GG * HH + 255) / 256, 256>>>();
    k_pool<<<(NN * 32 + 255) / 256, 256>>>(batch);
    k_out<<<1, 256>>>(out_w1, out_b1, out_w2, out_b2, out);
}

// round 15
// speedup vs baseline: 1.1775x; 1.1775x over previous
#include <cuda_runtime.h>
#include <cstdint>

// Problem constants (fixed by the dataset)
#define NN 30000
#define EE 600000
#define HH 128
#define GG 64
#define LL 4

#define TILE 64        // rows per CTA (all MMA kernels)
#define AS 260         // node-kernel sA stride (words)
#define AS2 132        // split-plane stride for K=128 tiles
#define KSTAGE 32      // W stage depth

// Scratch (device globals: allocation-free rule)
__device__ __align__(16) float g_dist[EE];
__device__ __align__(16) float g_h[NN * HH];
__device__ __align__(16) float g_aggr[NN * HH];
__device__ __align__(16) float g_pool[GG * HH];
__device__ __align__(16) float g_U[NN * HH];   // h @ msgW1[0:128]   + b1
__device__ __align__(16) float g_V[NN * HH];   // h @ msgW1[128:256]

// Pre-split tf32 weights (hi/lo planes)
#define MSGW1_N (LL * 257 * HH)
#define MSGW2_N (LL * HH * HH)
#define NODW1_N (LL * 2 * HH * HH)
#define NODW2_N (LL * HH * HH)
__device__ __align__(16) uint32_t g_mw1h[MSGW1_N], g_mw1l[MSGW1_N];
__device__ __align__(16) uint32_t g_mw2h[MSGW2_N], g_mw2l[MSGW2_N];
__device__ __align__(16) uint32_t g_nw1h[NODW1_N], g_nw1l[NODW1_N];
__device__ __align__(16) uint32_t g_nw2h[NODW2_N], g_nw2l[NODW2_N];

__device__ __forceinline__ float silu_f(float x) {
    return __fdividef(x, 1.0f + __expf(-x));
}
__device__ __forceinline__ uint32_t f2tf32(float f) {
    uint32_t r; asm("cvt.rna.tf32.f32 %0, %1;" : "=r"(r) : "f"(f)); return r;
}
__device__ __forceinline__ void split_tf32(float v, uint32_t& hi, uint32_t& lo) {
    hi = f2tf32(v);
    lo = f2tf32(v - __uint_as_float(hi));
}
__device__ __forceinline__ void mma_tf32(float (&d)[4], const uint32_t (&a)[4],
                                         const uint32_t (&b)[2]) {
    asm volatile(
        "mma.sync.aligned.m16n8k8.row.col.f32.tf32.tf32.f32 "
        "{%0,%1,%2,%3}, {%4,%5,%6,%7}, {%8,%9}, {%0,%1,%2,%3};"
        : "+f"(d[0]), "+f"(d[1]), "+f"(d[2]), "+f"(d[3])
        : "r"(a[0]), "r"(a[1]), "r"(a[2]), "r"(a[3]), "r"(b[0]), "r"(b[1]));
}
__device__ __forceinline__ void red2(float* p, float a, float b) {
    asm volatile("red.global.add.v2.f32 [%0], {%1,%2};" :: "l"(p), "f"(a), "f"(b) : "memory");
}
__device__ __forceinline__ void red4(float* p, float a, float b, float c, float d) {
    asm volatile("red.global.add.v4.f32 [%0], {%1,%2,%3,%4};"
                 :: "l"(p), "f"(a), "f"(b), "f"(c), "f"(d) : "memory");
}

__global__ void k_split(const float* __restrict__ src, uint32_t* __restrict__ hi,
                        uint32_t* __restrict__ lo, int n) {
    int i = blockIdx.x * blockDim.x + threadIdx.x;
    if (i >= n) return;
    uint32_t h, l;
    split_tf32(src[i], h, l);
    hi[i] = h; lo[i] = l;
}

// ---- W staging, software-pipelined: LDG into regs (wload), STS later (wstore)
__device__ __forceinline__ void wload(uint4 (&ph)[4], uint4 (&pl)[4],
                                      const uint32_t* __restrict__ wh,
                                      const uint32_t* __restrict__ wl,
                                      int k0, int tid) {
    #pragma unroll
    for (int i = 0; i < 4; i++) {
        int k = (tid >> 5) + 8 * i;          // 0..31
        int n0 = (tid & 31) * 4;
        ph[i] = *(const uint4*)(wh + (size_t)(k0 + k) * HH + n0);
        pl[i] = *(const uint4*)(wl + (size_t)(k0 + k) * HH + n0);
    }
}
__device__ __forceinline__ void wstore(const uint4 (&ph)[4], const uint4 (&pl)[4],
                                       float* sWh, float* sWl, int tid) {
    #pragma unroll
    for (int i = 0; i < 4; i++) {
        int k = (tid >> 5) + 8 * i;
        int n0 = (tid & 31) * 4;
        int d = k * HH + (n0 ^ ((k & 3) << 3));
        *(uint4*)(sWh + d) = ph[i];
        *(uint4*)(sWl + d) = pl[i];
    }
}

// One k8 step with PRE-SPLIT A planes (stride AS2): pure LDS+HMMA.
__device__ __forceinline__ void mma_k8ps(const float* sAh, const float* sAl,
                                         const float* sWh, const float* sWl,
                                         int mbase, int nbase, int kg, int kw,
                                         int gid, int kk, float (&acc)[2][4][4]) {
    uint32_t ah[2][4], al[2][4];
    #pragma unroll
    for (int i = 0; i < 2; i++) {
        int base = (mbase + i * 16 + gid) * AS2 + kg + kk;
        ah[i][0] = __float_as_uint(sAh[base]);
        ah[i][1] = __float_as_uint(sAh[base + 8 * AS2]);
        ah[i][2] = __float_as_uint(sAh[base + 4]);
        ah[i][3] = __float_as_uint(sAh[base + 8 * AS2 + 4]);
        al[i][0] = __float_as_uint(sAl[base]);
        al[i][1] = __float_as_uint(sAl[base + 8 * AS2]);
        al[i][2] = __float_as_uint(sAl[base + 4]);
        al[i][3] = __float_as_uint(sAl[base + 8 * AS2 + 4]);
    }
    const int rb = (kw + kk) * HH;
    #pragma unroll
    for (int j = 0; j < 4; j++) {
        int nsw = rb + ((nbase + j * 8 + gid) ^ (kk << 3));
        uint32_t bh[2], bl[2];
        bh[0] = __float_as_uint(sWh[nsw]);
        bh[1] = __float_as_uint(sWh[4 * HH + nsw]);
        bl[0] = __float_as_uint(sWl[nsw]);
        bl[1] = __float_as_uint(sWl[4 * HH + nsw]);
        mma_tf32(acc[0][j], ah[0], bh);
        mma_tf32(acc[0][j], ah[0], bl);
        mma_tf32(acc[0][j], al[0], bh);
        mma_tf32(acc[1][j], ah[1], bh);
        mma_tf32(acc[1][j], ah[1], bl);
        mma_tf32(acc[1][j], al[1], bh);
    }
}

// In-loop-split variant (node kernel; A fp32, stride AS).
__device__ __forceinline__ void mma_k8(const float* sA, const float* sWh, const float* sWl,
                                       int mbase, int nbase, int kg, int kw,
                                       int gid, int kk, float (&acc)[2][4][4]) {
    uint32_t ah[2][4], al[2][4];
    #pragma unroll
    for (int i = 0; i < 2; i++) {
        const float* ra = sA + (mbase + i * 16 + gid) * AS + kg + kk;
        split_tf32(ra[0],          ah[i][0], al[i][0]);
        split_tf32(ra[8 * AS],     ah[i][1], al[i][1]);
        split_tf32(ra[4],          ah[i][2], al[i][2]);
        split_tf32(ra[8 * AS + 4], ah[i][3], al[i][3]);
    }
    const int rb = (kw + kk) * HH;
    #pragma unroll
    for (int j = 0; j < 4; j++) {
        int nsw = rb + ((nbase + j * 8 + gid) ^ (kk << 3));
        uint32_t bh[2], bl[2];
        bh[0] = __float_as_uint(sWh[nsw]);
        bh[1] = __float_as_uint(sWh[4 * HH + nsw]);
        bl[0] = __float_as_uint(sWl[nsw]);
        bl[1] = __float_as_uint(sWl[4 * HH + nsw]);
        mma_tf32(acc[0][j], ah[0], bh);
        mma_tf32(acc[0][j], ah[0], bl);
        mma_tf32(acc[0][j], al[0], bh);
        mma_tf32(acc[1][j], ah[1], bh);
        mma_tf32(acc[1][j], ah[1], bl);
        mma_tf32(acc[1][j], al[1], bh);
    }
}

// ---------------------------------------------------------------------------
__global__ void k_dist(const float* __restrict__ pos, const int* __restrict__ ei) {
    int e = blockIdx.x * blockDim.x + threadIdx.x;
    if (e >= EE) return;
    int r = ei[e], c = ei[EE + e];
    float dx = pos[r * 3 + 0] - pos[c * 3 + 0];
    float dy = pos[r * 3 + 1] - pos[c * 3 + 1];
    float dz = pos[r * 3 + 2] - pos[c * 3 + 2];
    g_dist[e] = dx * dx + dy * dy + dz * dz;
}
__global__ void k_embed(const float* __restrict__ x, const float* __restrict__ w,
                        const float* __restrict__ b) {
    int i = blockIdx.x * blockDim.x + threadIdx.x;
    if (i >= NN * HH) return;
    int n = i >> 7, c = i & 127;
    g_h[i] = x[n] * w[c] + b[c];
}
__global__ void k_zero_pool() {
    int i = blockIdx.x * blockDim.x + threadIdx.x;
    if (i < GG * HH) g_pool[i] = 0.0f;
}

// ---------------------------------------------------------------------------
// Per-node precompute: U = h @ W1[0:128] + b1, V = h @ W1[128:256].
// Also zeroes g_aggr for this node tile (replaces k_zero_aggr).
__global__ __launch_bounds__(256, 2) void k_uv(
    const uint32_t* __restrict__ w1h, const uint32_t* __restrict__ w1l,
    const float* __restrict__ b1)
{
    extern __shared__ float sm[];
    float* sAh = sm;                         // TILE*AS2
    float* sAl = sAh + TILE * AS2;
    float* sWh = sAl + TILE * AS2;           // KSTAGE*HH
    float* sWl = sWh + KSTAGE * HH;
    float* sB1 = sWl + KSTAGE * HH;          // 128

    const int tid = threadIdx.x, wid = tid >> 5, lane = tid & 31;
    const int kk = lane & 3, gid = lane >> 2;
    const int mbase = (wid & 1) * 32;
    const int nbase = (wid >> 1) * 32;
    const int rbase = blockIdx.x * TILE;

    uint4 ph[4], pl[4];
    wload(ph, pl, w1h, w1l, 0, tid);         // prefetch chunk0 (overlaps gather)

    #pragma unroll
    for (int i = 0; i < 8; i++) {
        int m = wid * 8 + i;
        int n = rbase + m;
        float4 v = make_float4(0.f, 0.f, 0.f, 0.f);
        if (n < NN) v = *(const float4*)(g_h + (size_t)n * HH + lane * 4);
        uint4 qh, ql;
        split_tf32(v.x, qh.x, ql.x); split_tf32(v.y, qh.y, ql.y);
        split_tf32(v.z, qh.z, ql.z); split_tf32(v.w, qh.w, ql.w);
        *(uint4*)(sAh + m * AS2 + lane * 4) = qh;
        *(uint4*)(sAl + m * AS2 + lane * 4) = ql;
        if (n < NN)
            *(float4*)(g_aggr + (size_t)n * HH + lane * 4) = make_float4(0.f, 0.f, 0.f, 0.f);
    }
    if (tid < HH) sB1[tid] = b1[tid];
    __syncthreads();   // sB1 + gather visible before acc init / MMA (round-14 bug fix)

    #pragma unroll
    for (int pass = 0; pass < 2; pass++) {
        float acc[2][4][4];
        #pragma unroll
        for (int j = 0; j < 4; j++) {
            int col = nbase + j * 8 + kk * 2;
            float v0 = pass ? 0.f : sB1[col];
            float v1 = pass ? 0.f : sB1[col + 1];
            acc[0][j][0] = v0; acc[0][j][1] = v1; acc[0][j][2] = v0; acc[0][j][3] = v1;
            acc[1][j][0] = v0; acc[1][j][1] = v1; acc[1][j][2] = v0; acc[1][j][3] = v1;
        }
        #pragma unroll
        for (int st = 0; st < 4; st++) {
            int k0 = st * KSTAGE;
            __syncthreads();
            wstore(ph, pl, sWh, sWl, tid);
            __syncthreads();
            // prefetch next chunk (next stage, or next pass's chunk 0)
            if (st < 3)
                wload(ph, pl, w1h + (size_t)pass * 128 * HH,
                      w1l + (size_t)pass * 128 * HH, k0 + KSTAGE, tid);
            else if (pass == 0)
                wload(ph, pl, w1h + (size_t)128 * HH, w1l + (size_t)128 * HH, 0, tid);
            #pragma unroll
            for (int c = 0; c < 4; c++)
                mma_k8ps(sAh, sAl, sWh, sWl, mbase, nbase, k0 + c * 8, c * 8, gid, kk, acc);
        }
        float* dst = pass ? g_V : g_U;
        #pragma unroll
        for (int i = 0; i < 2; i++) {
            int r0 = mbase + i * 16 + gid, r1 = r0 + 8;
            int n0 = rbase + r0, n1 = rbase + r1;
            #pragma unroll
            for (int j = 0; j < 4; j++) {
                int col = nbase + j * 8 + kk * 2;
                if (n0 < NN)
                    *(float2*)(dst + (size_t)n0 * HH + col) = make_float2(acc[i][j][0], acc[i][j][1]);
                if (n1 < NN)
                    *(float2*)(dst + (size_t)n1 * HH + col) = make_float2(acc[i][j][2], acc[i][j][3]);
            }
        }
    }
}

// ---------------------------------------------------------------------------
// Edge kernel: 64 edges/CTA, 256 threads (8 warps, 2M x 4N), prefetched W.
// pre = U[dst]+V[src]+d2*w1r -> silu -> split -> GEMM2 (K=128) -> scatter.
__global__ __launch_bounds__(256, 2) void k_edge(
    const int* __restrict__ ei,
    const uint32_t* __restrict__ w2h, const uint32_t* __restrict__ w2l,
    const float* __restrict__ w1, const float* __restrict__ b2)
{
    extern __shared__ float sm[];
    float* sAh = sm;                          // TILE*AS2
    float* sAl = sAh + TILE * AS2;
    float* sWh = sAl + TILE * AS2;            // KSTAGE*HH
    float* sWl = sWh + KSTAGE * HH;
    int* sCol = (int*)(sWl + KSTAGE * HH);    // 64
    float* sW1r = (float*)(sCol + TILE);      // 128
    float* sB2 = sW1r + HH;                   // 128

    const int tid = threadIdx.x, wid = tid >> 5, lane = tid & 31;
    const int kk = lane & 3, gid = lane >> 2;
    const int mbase = (wid & 1) * 32;
    const int nbase = (wid >> 1) * 32;
    const int e0 = blockIdx.x * TILE;

    uint4 ph[4], pl[4];
    wload(ph, pl, w2h, w2l, 0, tid);          // prefetch chunk0 (overlaps gather)

    if (tid < HH) {
        sW1r[tid] = w1[(size_t)256 * HH + tid];
        sB2[tid] = b2[tid];
    }
    __syncthreads();

    // gather + message pre-activation + silu + split
    #pragma unroll
    for (int i = 0; i < 8; i++) {
        int m = wid * 8 + i;
        int e = e0 + m;
        int src = ei[e], dst = ei[EE + e];
        if (lane == 0) sCol[m] = dst;
        float d = g_dist[e];
        float4 u = *(const float4*)(g_U + (size_t)dst * HH + lane * 4);
        float4 v = *(const float4*)(g_V + (size_t)src * HH + lane * 4);
        float4 wr = *(const float4*)(sW1r + lane * 4);
        float4 t;
        t.x = silu_f(u.x + v.x + d * wr.x);
        t.y = silu_f(u.y + v.y + d * wr.y);
        t.z = silu_f(u.z + v.z + d * wr.z);
        t.w = silu_f(u.w + v.w + d * wr.w);
        uint4 qh, ql;
        split_tf32(t.x, qh.x, ql.x); split_tf32(t.y, qh.y, ql.y);
        split_tf32(t.z, qh.z, ql.z); split_tf32(t.w, qh.w, ql.w);
        *(uint4*)(sAh + m * AS2 + lane * 4) = qh;
        *(uint4*)(sAl + m * AS2 + lane * 4) = ql;
    }

    float acc[2][4][4];
    #pragma unroll
    for (int j = 0; j < 4; j++) {
        int col = nbase + j * 8 + kk * 2;
        float v0 = sB2[col], v1 = sB2[col + 1];
        acc[0][j][0] = v0; acc[0][j][1] = v1; acc[0][j][2] = v0; acc[0][j][3] = v1;
        acc[1][j][0] = v0; acc[1][j][1] = v1; acc[1][j][2] = v0; acc[1][j][3] = v1;
    }

    // GEMM2: K = 128 in 4 prefetched stages of 32
    #pragma unroll
    for (int st = 0; st < 4; st++) {
        int k0 = st * KSTAGE;
        __syncthreads();                       // also covers gather completion at st=0
        wstore(ph, pl, sWh, sWl, tid);
        __syncthreads();
        if (st < 3) wload(ph, pl, w2h, w2l, k0 + KSTAGE, tid);
        #pragma unroll
        for (int c = 0; c < 4; c++)
            mma_k8ps(sAh, sAl, sWh, sWl, mbase, nbase, k0 + c * 8, c * 8, gid, kk, acc);
    }

    // scatter-add into g_aggr[dst]
    #pragma unroll
    for (int i = 0; i < 2; i++) {
        int r0 = mbase + i * 16 + gid, r1 = r0 + 8;
        float* p0 = g_aggr + (size_t)sCol[r0] * HH;
        float* p1 = g_aggr + (size_t)sCol[r1] * HH;
        #pragma unroll
        for (int j = 0; j < 4; j++) {
            int col = nbase + j * 8 + kk * 2;
            red2(p0 + col, acc[i][j][0], acc[i][j][1]);
            red2(p1 + col, acc[i][j][2], acc[i][j][3]);
        }
    }
}

// ---------------------------------------------------------------------------
// Fused node MLP (3xTF32 mma.sync, pre-split W, prefetched). A = [h | aggr].
__global__ __launch_bounds__(256, 2) void k_node(
    const uint32_t* __restrict__ w1h, const uint32_t* __restrict__ w1l,
    const uint32_t* __restrict__ w2h, const uint32_t* __restrict__ w2l,
    const float* __restrict__ b1, const float* __restrict__ b2)
{
    extern __shared__ float sm[];
    float* sA = sm;
    float* sWh = sm + TILE * AS;
    float* sWl = sWh + KSTAGE * HH;
    float* sB1 = sWl + KSTAGE * HH;
    float* sB2 = sB1 + HH;

    const int tid = threadIdx.x, wid = tid >> 5, lane = tid & 31;
    const int kk = lane & 3, gid = lane >> 2;
    const int mbase = (wid & 1) * 32;
    const int nbase = (wid >> 1) * 32;
    const int rbase = blockIdx.x * TILE;

    uint4 ph[4], pl[4];
    wload(ph, pl, w1h, w1l, 0, tid);

    #pragma unroll
    for (int i = 0; i < 8; i++) {
        int m = wid * 8 + i;
        int n = rbase + m;
        float4 vh = make_float4(0.f, 0.f, 0.f, 0.f), va = vh;
        if (n < NN) {
            vh = *(const float4*)(g_h + (size_t)n * HH + lane * 4);
            va = *(const float4*)(g_aggr + (size_t)n * HH + lane * 4);
        }
        *(float4*)(sA + m * AS + lane * 4) = vh;
        *(float4*)(sA + m * AS + 128 + lane * 4) = va;
    }
    if (tid < HH) { sB1[tid] = b1[tid]; sB2[tid] = b2[tid]; }

    float acc[2][4][4];
    __syncthreads();   // gather + biases visible
    #pragma unroll
    for (int j = 0; j < 4; j++) {
        int col = nbase + j * 8 + kk * 2;
        float v0 = sB1[col], v1 = sB1[col + 1];
        acc[0][j][0] = v0; acc[0][j][1] = v1; acc[0][j][2] = v0; acc[0][j][3] = v1;
        acc[1][j][0] = v0; acc[1][j][1] = v1; acc[1][j][2] = v0; acc[1][j][3] = v1;
    }

    // GEMM1: K = 256, 8 prefetched stages
    #pragma unroll
    for (int st = 0; st < 8; st++) {
        int k0 = st * KSTAGE;
        __syncthreads();
        wstore(ph, pl, sWh, sWl, tid);
        __syncthreads();
        if (st < 7) wload(ph, pl, w1h, w1l, k0 + KSTAGE, tid);
        else        wload(ph, pl, w2h, w2l, 0, tid);   // chain into GEMM2
        #pragma unroll
        for (int c = 0; c < 4; c++)
            mma_k8(sA, sWh, sWl, mbase, nbase, k0 + c * 8, c * 8, gid, kk, acc);
    }
    __syncthreads();

    #pragma unroll
    for (int i = 0; i < 2; i++) {
        int r0 = mbase + i * 16 + gid, r1 = r0 + 8;
        #pragma unroll
        for (int j = 0; j < 4; j++) {
            int col = nbase + j * 8 + kk * 2;
            float t0 = silu_f(acc[i][j][0]);
            float t1 = silu_f(acc[i][j][1]);
            float t2 = silu_f(acc[i][j][2]);
            float t3 = silu_f(acc[i][j][3]);
            *(float2*)(sA + r0 * AS + col) = make_float2(t0, t1);
            *(float2*)(sA + r1 * AS + col) = make_float2(t2, t3);
            float b0 = sB2[col], b1v = sB2[col + 1];
            acc[i][j][0] = b0; acc[i][j][1] = b1v; acc[i][j][2] = b0; acc[i][j][3] = b1v;
        }
    }

    // GEMM2: K = 128, 4 prefetched stages
    #pragma unroll
    for (int st = 0; st < 4; st++) {
        int k0 = st * KSTAGE;
        __syncthreads();
        wstore(ph, pl, sWh, sWl, tid);
        __syncthreads();
        if (st < 3) wload(ph, pl, w2h, w2l, k0 + KSTAGE, tid);
        #pragma unroll
        for (int c = 0; c < 4; c++)
            mma_k8(sA, sWh, sWl, mbase, nbase, k0 + c * 8, c * 8, gid, kk, acc);
    }

    #pragma unroll
    for (int i = 0; i < 2; i++) {
        int r0 = mbase + i * 16 + gid, r1 = r0 + 8;
        int n0 = rbase + r0, n1 = rbase + r1;
        #pragma unroll
        for (int j = 0; j < 4; j++) {
            int col = nbase + j * 8 + kk * 2;
            if (n0 < NN)
                *(float2*)(g_h + (size_t)n0 * HH + col) = make_float2(acc[i][j][0], acc[i][j][1]);
            if (n1 < NN)
                *(float2*)(g_h + (size_t)n1 * HH + col) = make_float2(acc[i][j][2], acc[i][j][3]);
        }
    }
}

// ---------------------------------------------------------------------------
__global__ void k_pool(const int* __restrict__ batch) {
    int i = blockIdx.x * blockDim.x + threadIdx.x;
    if (i >= NN * 32) return;
    int n = i >> 5, c4 = (i & 31) * 4;
    int b = batch[n];
    const float* hr = g_h + (size_t)n * HH + c4;
    red4(g_pool + (size_t)b * HH + c4, hr[0], hr[1], hr[2], hr[3]);
}

__global__ void k_out(const float* __restrict__ w1, const float* __restrict__ b1,
                      const float* __restrict__ w2, const float* __restrict__ b2,
                      float* __restrict__ out) {
    __shared__ float sg[GG * HH];
    __shared__ float sh[GG * 32];
    int tid = threadIdx.x;
    for (int i = tid; i < GG * HH; i += 256) sg[i] = g_pool[i];
    __syncthreads();
    for (int p = tid; p < GG * 32; p += 256) {
        int g = p >> 5, j = p & 31;
        float s = b1[j];
        #pragma unroll 4
        for (int k = 0; k < HH; k++) s += sg[g * HH + k] * w1[k * 32 + j];
        sh[p] = silu_f(s);
    }
    __syncthreads();
    if (tid < GG) {
        float s = b2[0];
        #pragma unroll
        for (int j = 0; j < 32; j++) s += sh[tid * 32 + j] * w2[j];
        out[tid] = s;
    }
}

// ---------------------------------------------------------------------------
extern "C" void kernel_launch(void* const* d_in, const int* in_sizes, int n_in,
                              void* d_out, int out_size) {
    const float* x       = (const float*)d_in[0];
    const float* pos     = (const float*)d_in[1];
    const int*   ei      = (const int*)d_in[2];
    const int*   batch   = (const int*)d_in[3];
    const float* emb_w   = (const float*)d_in[4];
    const float* emb_b   = (const float*)d_in[5];
    const float* msg_w1  = (const float*)d_in[6];
    const float* msg_b1  = (const float*)d_in[7];
    const float* msg_w2  = (const float*)d_in[8];
    const float* msg_b2  = (const float*)d_in[9];
    const float* node_w1 = (const float*)d_in[10];
    const float* node_b1 = (const float*)d_in[11];
    const float* node_w2 = (const float*)d_in[12];
    const float* node_b2 = (const float*)d_in[13];
    const float* out_w1  = (const float*)d_in[14];
    const float* out_b1  = (const float*)d_in[15];
    const float* out_w2  = (const float*)d_in[16];
    const float* out_b2  = (const float*)d_in[17];
    float* out = (float*)d_out;

    const int SMEM_UV   = (2 * TILE * AS2 + 2 * KSTAGE * HH + HH) * 4;
    const int SMEM_EDGE = (2 * TILE * AS2 + 2 * KSTAGE * HH) * 4 + TILE * 4 + 2 * HH * 4;
    const int SMEM_NODE = (TILE * AS + 2 * KSTAGE * HH) * 4 + 2 * HH * 4;
    cudaFuncSetAttribute(k_uv, cudaFuncAttributeMaxDynamicSharedMemorySize, SMEM_UV);
    cudaFuncSetAttribute(k_edge, cudaFuncAttributeMaxDynamicSharedMemorySize, SMEM_EDGE);
    cudaFuncSetAttribute(k_node, cudaFuncAttributeMaxDynamicSharedMemorySize, SMEM_NODE);

    void *mw1h, *mw1l, *mw2h, *mw2l, *nw1h, *nw1l, *nw2h, *nw2l;
    cudaGetSymbolAddress(&mw1h, g_mw1h); cudaGetSymbolAddress(&mw1l, g_mw1l);
    cudaGetSymbolAddress(&mw2h, g_mw2h); cudaGetSymbolAddress(&mw2l, g_mw2l);
    cudaGetSymbolAddress(&nw1h, g_nw1h); cudaGetSymbolAddress(&nw1l, g_nw1l);
    cudaGetSymbolAddress(&nw2h, g_nw2h); cudaGetSymbolAddress(&nw2l, g_nw2l);

    k_split<<<(MSGW1_N + 255) / 256, 256>>>(msg_w1, (uint32_t*)mw1h, (uint32_t*)mw1l, MSGW1_N);
    k_split<<<(MSGW2_N + 255) / 256, 256>>>(msg_w2, (uint32_t*)mw2h, (uint32_t*)mw2l, MSGW2_N);
    k_split<<<(NODW1_N + 255) / 256, 256>>>(node_w1, (uint32_t*)nw1h, (uint32_t*)nw1l, NODW1_N);
    k_split<<<(NODW2_N + 255) / 256, 256>>>(node_w2, (uint32_t*)nw2h, (uint32_t*)nw2l, NODW2_N);

    k_dist<<<(EE + 255) / 256, 256>>>(pos, ei);
    k_embed<<<(NN * HH + 255) / 256, 256>>>(x, emb_w, emb_b);

    const int EGRID = EE / TILE;                 // 9375 (exact)
    const int NGRID = (NN + TILE - 1) / TILE;    // 469

    for (int l = 0; l < LL; l++) {
        k_uv<<<NGRID, 256, SMEM_UV>>>(
            (const uint32_t*)mw1h + (size_t)l * 257 * HH,
            (const uint32_t*)mw1l + (size_t)l * 257 * HH,
            msg_b1 + (size_t)l * HH);
        k_edge<<<EGRID, 256, SMEM_EDGE>>>(
            ei,
            (const uint32_t*)mw2h + (size_t)l * HH * HH,
            (const uint32_t*)mw2l + (size_t)l * HH * HH,
            msg_w1 + (size_t)l * 257 * HH,
            msg_b2 + (size_t)l * HH);
        k_node<<<NGRID, 256, SMEM_NODE>>>(
            (const uint32_t*)nw1h + (size_t)l * 2 * HH * HH,
            (const uint32_t*)nw1l + (size_t)l * 2 * HH * HH,
            (const uint32_t*)nw2h + (size_t)l * HH * HH,
            (const uint32_t*)nw2l + (size_t)l * HH * HH,
            node_b1 + (size_t)l * HH, node_b2 + (size_t)l * HH);
    }

    k_zero_pool<<<(GG * HH + 255) / 256, 256>>>();
    k_pool<<<(NN * 32 + 255) / 256, 256>>>(batch);
    k_out<<<1, 256>>>(out_w1, out_b1, out_w2, out_b2, out);
}